// round 15
// baseline (speedup 1.0000x reference)
#include <cuda_runtime.h>
#include <cuda_fp16.h>
#include <cstdint>

#define B_ROWS 8192
#define H_DIM  1024
#define L_DIM  1024
#define NHEADS 5

#define BM 128
#define BN 128
#define KS 32                    // K elements per stage
#define NC (H_DIM / KS)          // 32 stages
#define MAX_MTILES 80
#define STAGE_BYTES 16384        // A 8K + B 8K
#define NSTAGE 4
#define SMEM_TOTAL (NSTAGE * STAGE_BYTES)   // 64 KB dynamic
#define NTHR 512

// ---------------- device scratch (static, no allocations) ----------------
__device__ int g_perm[B_ROWS];
__device__ int g_tileGroup[MAX_MTILES];
__device__ int g_tileBase[MAX_MTILES];
__device__ int g_tileCnt[MAX_MTILES];

__device__ __half g_hid[B_ROWS * H_DIM];
__device__ __half g_W[NHEADS * L_DIM * H_DIM];

// ---------------- helpers ----------------
__device__ __forceinline__ uint32_t smem_u32(const void* p) {
    uint32_t a;
    asm("{ .reg .u64 t; cvta.to.shared.u64 t, %1; cvt.u32.u64 %0, t; }" : "=r"(a) : "l"(p));
    return a;
}

#define LDSM_X4(r, addr) \
    asm volatile("ldmatrix.sync.aligned.m8n8.x4.shared.b16 {%0,%1,%2,%3}, [%4];" \
        : "=r"((r)[0]), "=r"((r)[1]), "=r"((r)[2]), "=r"((r)[3]) : "r"(addr))

#define CP_ASYNC16(dst, src, sz) \
    asm volatile("cp.async.cg.shared.global [%0], [%1], 16, %2;" \
        :: "r"(dst), "l"(src), "r"(sz) : "memory")
#define CP_COMMIT() asm volatile("cp.async.commit_group;" ::: "memory")
#define CP_WAIT2()  asm volatile("cp.async.wait_group 2;" ::: "memory")
#define CP_WAIT1()  asm volatile("cp.async.wait_group 1;" ::: "memory")
#define CP_WAIT0()  asm volatile("cp.async.wait_group 0;" ::: "memory")

// fp16-accumulate HMMA: D,C are 2x f16x2 regs
__device__ __forceinline__ void mma16816h(uint32_t* d, const uint32_t* a, uint32_t b0, uint32_t b1) {
    asm volatile(
        "mma.sync.aligned.m16n8k16.row.col.f16.f16.f16.f16 "
        "{%0,%1}, {%2,%3,%4,%5}, {%6,%7}, {%0,%1};"
        : "+r"(d[0]), "+r"(d[1])
        : "r"(a[0]), "r"(a[1]), "r"(a[2]), "r"(a[3]), "r"(b0), "r"(b1));
}

// swizzled byte offset within a 128-row x 64-byte tile
__device__ __forceinline__ uint32_t swz(int row, int chunk) {
    return (uint32_t)(row * 64 + ((chunk ^ ((row >> 1) & 3)) << 4));
}

__device__ __forceinline__ uint32_t pack2(__half a, __half b) {
    return (uint32_t)__half_as_ushort(a) | ((uint32_t)__half_as_ushort(b) << 16);
}

// ---------------- fused prep: count + plan + scatter (single block, 1024 thr) ----------------
__global__ void k_prep(const int* __restrict__ group) {
    __shared__ int s_cnt[8], s_off[8];
    int tid = threadIdx.x;
    if (tid < 8) s_cnt[tid] = 0;
    __syncthreads();
    int g[8];
    #pragma unroll
    for (int i = 0; i < 8; i++) {
        int row = tid + 1024 * i;
        int gg = group[row]; gg = gg < 0 ? 0 : (gg > 5 ? 5 : gg);
        g[i] = gg;
        atomicAdd(&s_cnt[gg], 1);
    }
    __syncthreads();
    if (tid == 0) {
        int off = 0;
        for (int k = 0; k < 6; k++) { s_off[k] = off; off += s_cnt[k]; }
        int t = 0;
        for (int k = 0; k < 6; k++) {       // includes group 5 (fill tiles)
            int c = s_cnt[k], o = s_off[k];
            for (int s = 0; s < c; s += BM) {
                g_tileGroup[t] = k; g_tileBase[t] = o + s;
                g_tileCnt[t] = (c - s) < BM ? (c - s) : BM; t++;
            }
        }
        for (; t < MAX_MTILES; t++) g_tileGroup[t] = -1;
        for (int k = 0; k < 6; k++) s_cnt[k] = s_off[k];   // reuse as cursors
    }
    __syncthreads();
    #pragma unroll
    for (int i = 0; i < 8; i++) {
        int row = tid + 1024 * i;
        int pos = atomicAdd(&s_cnt[g[i]], 1);
        g_perm[pos] = row;
    }
}

// ---------------- fused fp16 conversion (W then hidden), 2 float4 per thread ----------------
#define NW4 (NHEADS * L_DIM * H_DIM / 4)    // 1310720 float4s
#define NH4 (B_ROWS * H_DIM / 4)            // 2097152 float4s

__global__ void k_cvt(const float* __restrict__ W, const float* __restrict__ hid) {
    int i0 = blockIdx.x * (blockDim.x * 2) + threadIdx.x;
    #pragma unroll
    for (int u = 0; u < 2; u++) {
        int i = i0 + u * 256;
        const float* src; __half* dst; int j;
        if (i < NW4) { src = W;   dst = g_W;   j = i; }
        else         { src = hid; dst = g_hid; j = i - NW4; }
        float4 v = reinterpret_cast<const float4*>(src)[j];
        uint2 hp = make_uint2(pack2(__float2half_rn(v.x), __float2half_rn(v.y)),
                              pack2(__float2half_rn(v.z), __float2half_rn(v.w)));
        reinterpret_cast<uint2*>(dst)[j] = hp;
    }
}

// ---------------- HMMA GEMM 128x128, 512 thr, warp tile 32x32, occ 2 (8 warps/SMSP) ----------------
__global__ __launch_bounds__(NTHR, 2)
void k_gemm_mma(const float* __restrict__ bias, const int* __restrict__ labels,
                float* __restrict__ out) {
    int t = blockIdx.y;
    int g = g_tileGroup[t];
    if (g < 0) return;
    int base = g_tileBase[t];
    int cnt  = g_tileCnt[t];
    int nBase = blockIdx.x * BN;
    int tid = threadIdx.x;

    if (g == 5) {
        // fill tile: each row gets broadcast label value over this 128-col slice
        for (int i = tid; i < cnt * 32; i += NTHR) {
            int r = i >> 5, c = i & 31;
            int gr = g_perm[base + r];
            float v = (float)labels[gr];
            float4 vv = make_float4(v, v, v, v);
            reinterpret_cast<float4*>(out + (size_t)gr * L_DIM + nBase)[c] = vv;
        }
        return;
    }

    extern __shared__ __align__(1024) char smem[];
    uint32_t sb = smem_u32(smem);

    int lane = tid & 31, wid = tid >> 5;
    int warp_m = wid & 3;        // M offset 32*warp_m
    int warp_n = wid >> 2;       // N offset 32*warp_n (0..3)

    // loader metadata: 1 A chunk + 1 B chunk per thread (512 x 16B = 8KB each)
    int lrow = tid >> 2;
    int lchk = tid & 3;
    int grow = (lrow < cnt) ? g_perm[base + lrow] : -1;
    uint32_t d0 = swz(lrow, lchk);
    const __half* aP = g_hid + (size_t)(grow < 0 ? 0 : grow) * H_DIM + lchk * 8;
    uint32_t szA = grow >= 0 ? 16u : 0u;
    const __half* bP = g_W + (size_t)(g * L_DIM + nBase + lrow) * H_DIM + lchk * 8;

    uint32_t acc[2][4][2];
    #pragma unroll
    for (int i = 0; i < 2; i++)
        #pragma unroll
        for (int j = 0; j < 4; j++) { acc[i][j][0] = 0u; acc[i][j][1] = 0u; }

    auto load_stage = [&](int c) {
        uint32_t s0 = sb + (uint32_t)(c & 3) * STAGE_BYTES;
        int kOff = c * KS;
        CP_ASYNC16(s0 + d0,        aP + kOff, szA);
        CP_ASYNC16(s0 + 8192 + d0, bP + kOff, 16u);
        CP_COMMIT();
    };

    load_stage(0);
    load_stage(1);
    load_stage(2);

    #pragma unroll 1
    for (int c = 0; c < NC; c++) {
        if (c + 2 < NC)      { CP_WAIT2(); }
        else if (c + 1 < NC) { CP_WAIT1(); }
        else                 { CP_WAIT0(); }
        __syncthreads();
        if (c + 3 < NC) load_stage(c + 3);

        uint32_t Ab = sb + (uint32_t)(c & 3) * STAGE_BYTES;
        uint32_t Bb = Ab + 8192;

        #pragma unroll
        for (int s = 0; s < 2; s++) {
            int ch = 2 * s + (lane >> 4);
            uint32_t b[2][4];
            #pragma unroll
            for (int nb = 0; nb < 2; nb++) {
                int row = warp_n * 32 + nb * 16 + (lane & 15);
                LDSM_X4(b[nb], Bb + swz(row, ch));
            }
            uint32_t a[2][4];
            #pragma unroll
            for (int mt = 0; mt < 2; mt++) {
                int row = warp_m * 32 + mt * 16 + (lane & 15);
                LDSM_X4(a[mt], Ab + swz(row, ch));
            }
            #pragma unroll
            for (int mt = 0; mt < 2; mt++)
                #pragma unroll
                for (int nt = 0; nt < 4; nt++) {
                    int nb = nt >> 1, hf = nt & 1;
                    mma16816h(acc[mt][nt], a[mt], b[nb][hf], b[nb][hf + 2]);
                }
        }
    }

    // ---- epilogue (unpack fp16 acc -> fp32, add bias, scatter) ----
    int rl = lane >> 2;
    int cl = (lane & 3) * 2;
    const float* bptr = bias + g * L_DIM + nBase + warp_n * 32 + cl;

    #pragma unroll
    for (int mt = 0; mt < 2; mt++)
        #pragma unroll
        for (int h = 0; h < 2; h++) {
            int r = warp_m * 32 + mt * 16 + rl + h * 8;
            int gr = (r < cnt) ? g_perm[base + r] : -1;
            if (gr < 0) continue;
            float* orow = out + (size_t)gr * L_DIM + nBase + warp_n * 32 + cl;
            #pragma unroll
            for (int nt = 0; nt < 4; nt++) {
                __half2 hv = *reinterpret_cast<__half2*>(&acc[mt][nt][h]);
                float2 fv = __half22float2(hv);
                float2 bv = *reinterpret_cast<const float2*>(bptr + nt * 8);
                float2 o;
                o.x = fv.x + bv.x;
                o.y = fv.y + bv.y;
                *reinterpret_cast<float2*>(orow + nt * 8) = o;
            }
        }
}

// ---------------- launch ----------------
extern "C" void kernel_launch(void* const* d_in, const int* in_sizes, int n_in,
                              void* d_out, int out_size) {
    const float* hidden = (const float*)d_in[0];
    const float* W      = (const float*)d_in[1];
    const float* bias   = (const float*)d_in[2];
    const int*   group  = (const int*)d_in[3];
    const int*   labels = (const int*)d_in[4];
    float* out = (float*)d_out;

    // one-time setup on the (uncaptured) correctness call; reused during capture
    static cudaStream_t s2 = nullptr;
    static cudaEvent_t e1 = nullptr, e2 = nullptr;
    if (!s2) {
        cudaStreamCreateWithFlags(&s2, cudaStreamNonBlocking);
        cudaEventCreateWithFlags(&e1, cudaEventDisableTiming);
        cudaEventCreateWithFlags(&e2, cudaEventDisableTiming);
        cudaFuncSetAttribute(k_gemm_mma, cudaFuncAttributeMaxDynamicSharedMemorySize, SMEM_TOTAL);
    }

    // fork: prep runs on side stream concurrent with cvt on main stream
    cudaEventRecord(e1, 0);
    cudaStreamWaitEvent(s2, e1, 0);
    k_prep<<<1, 1024, 0, s2>>>(group);
    cudaEventRecord(e2, s2);

    k_cvt<<<(NW4 + NH4) / 512, 256>>>(W, hidden);

    // join: gemm waits for both
    cudaStreamWaitEvent(0, e2, 0);
    dim3 grid(L_DIM / BN, MAX_MTILES);
    k_gemm_mma<<<grid, NTHR, SMEM_TOTAL>>>(bias, labels, out);
}

// round 16
// speedup vs baseline: 1.0777x; 1.0777x over previous
#include <cuda_runtime.h>
#include <cuda_fp16.h>
#include <cstdint>

#define B_ROWS 8192
#define H_DIM  1024
#define L_DIM  1024
#define NHEADS 5

#define BM 64
#define BN 128
#define KS 32                    // K elements per stage
#define NC (H_DIM / KS)          // 32 stages
#define MAX_MTILES 144
#define A_BYTES 4096
#define B_BYTES 8192
#define STAGE_BYTES (A_BYTES + B_BYTES)     // 12 KB
#define NSTAGE 3
#define SMEM_TOTAL (NSTAGE * STAGE_BYTES)   // 36 KB -> 6 CTAs/SM
#define NTHR 128

// ---------------- device scratch (static, no allocations) ----------------
__device__ int g_perm[B_ROWS];
__device__ int g_tileGroup[MAX_MTILES];
__device__ int g_tileBase[MAX_MTILES];
__device__ int g_tileCnt[MAX_MTILES];

__device__ __half g_hid[B_ROWS * H_DIM];
__device__ __half g_W[NHEADS * L_DIM * H_DIM];

// ---------------- helpers ----------------
__device__ __forceinline__ uint32_t smem_u32(const void* p) {
    uint32_t a;
    asm("{ .reg .u64 t; cvta.to.shared.u64 t, %1; cvt.u32.u64 %0, t; }" : "=r"(a) : "l"(p));
    return a;
}

#define LDSM_X4(r, addr) \
    asm volatile("ldmatrix.sync.aligned.m8n8.x4.shared.b16 {%0,%1,%2,%3}, [%4];" \
        : "=r"((r)[0]), "=r"((r)[1]), "=r"((r)[2]), "=r"((r)[3]) : "r"(addr))

#define CP_ASYNC16(dst, src, sz) \
    asm volatile("cp.async.cg.shared.global [%0], [%1], 16, %2;" \
        :: "r"(dst), "l"(src), "r"(sz) : "memory")
#define CP_COMMIT() asm volatile("cp.async.commit_group;" ::: "memory")
#define CP_WAIT1()  asm volatile("cp.async.wait_group 1;" ::: "memory")
#define CP_WAIT0()  asm volatile("cp.async.wait_group 0;" ::: "memory")

// fp16-accumulate HMMA: D,C are 2x f16x2 regs
__device__ __forceinline__ void mma16816h(uint32_t* d, const uint32_t* a, uint32_t b0, uint32_t b1) {
    asm volatile(
        "mma.sync.aligned.m16n8k16.row.col.f16.f16.f16.f16 "
        "{%0,%1}, {%2,%3,%4,%5}, {%6,%7}, {%0,%1};"
        : "+r"(d[0]), "+r"(d[1])
        : "r"(a[0]), "r"(a[1]), "r"(a[2]), "r"(a[3]), "r"(b0), "r"(b1));
}

// swizzled byte offset within a tile of 64B rows
__device__ __forceinline__ uint32_t swz(int row, int chunk) {
    return (uint32_t)(row * 64 + ((chunk ^ ((row >> 1) & 3)) << 4));
}

__device__ __forceinline__ uint32_t pack2(__half a, __half b) {
    return (uint32_t)__half_as_ushort(a) | ((uint32_t)__half_as_ushort(b) << 16);
}

// ---------------- fused prep: count + plan + scatter (single block, 1024 thr) ----------------
__global__ void k_prep(const int* __restrict__ group) {
    __shared__ int s_cnt[8], s_off[8];
    int tid = threadIdx.x;
    if (tid < 8) s_cnt[tid] = 0;
    __syncthreads();
    int g[8];
    #pragma unroll
    for (int i = 0; i < 8; i++) {
        int row = tid + 1024 * i;
        int gg = group[row]; gg = gg < 0 ? 0 : (gg > 5 ? 5 : gg);
        g[i] = gg;
        atomicAdd(&s_cnt[gg], 1);
    }
    __syncthreads();
    if (tid == 0) {
        int off = 0;
        for (int k = 0; k < 6; k++) { s_off[k] = off; off += s_cnt[k]; }
        int t = 0;
        for (int k = 0; k < 6; k++) {       // includes group 5 (fill tiles)
            int c = s_cnt[k], o = s_off[k];
            for (int s = 0; s < c; s += BM) {
                g_tileGroup[t] = k; g_tileBase[t] = o + s;
                g_tileCnt[t] = (c - s) < BM ? (c - s) : BM; t++;
            }
        }
        for (; t < MAX_MTILES; t++) g_tileGroup[t] = -1;
        for (int k = 0; k < 6; k++) s_cnt[k] = s_off[k];   // reuse as cursors
    }
    __syncthreads();
    #pragma unroll
    for (int i = 0; i < 8; i++) {
        int row = tid + 1024 * i;
        int pos = atomicAdd(&s_cnt[g[i]], 1);
        g_perm[pos] = row;
    }
}

// ---------------- fused fp16 conversion (W then hidden), 2 float4 per thread ----------------
#define NW4 (NHEADS * L_DIM * H_DIM / 4)    // 1310720 float4s
#define NH4 (B_ROWS * H_DIM / 4)            // 2097152 float4s

__global__ void k_cvt(const float* __restrict__ W, const float* __restrict__ hid) {
    int i0 = blockIdx.x * (blockDim.x * 2) + threadIdx.x;
    #pragma unroll
    for (int u = 0; u < 2; u++) {
        int i = i0 + u * 256;
        const float* src; __half* dst; int j;
        if (i < NW4) { src = W;   dst = g_W;   j = i; }
        else         { src = hid; dst = g_hid; j = i - NW4; }
        float4 v = reinterpret_cast<const float4*>(src)[j];
        uint2 hp = make_uint2(pack2(__float2half_rn(v.x), __float2half_rn(v.y)),
                              pack2(__float2half_rn(v.z), __float2half_rn(v.w)));
        reinterpret_cast<uint2*>(dst)[j] = hp;
    }
}

// ---------------- HMMA GEMM 64x128, 128 thr (warp 32x64), 6 CTAs/SM ----------------
__global__ __launch_bounds__(NTHR, 6)
void k_gemm_mma(const float* __restrict__ bias, const int* __restrict__ labels,
                float* __restrict__ out) {
    int t = blockIdx.y;
    int g = g_tileGroup[t];
    if (g < 0) return;
    int base = g_tileBase[t];
    int cnt  = g_tileCnt[t];
    int nBase = blockIdx.x * BN;
    int tid = threadIdx.x;

    if (g == 5) {
        // fill tile: each row gets broadcast label value over this 128-col slice
        for (int i = tid; i < cnt * 32; i += NTHR) {
            int r = i >> 5, c = i & 31;
            int gr = g_perm[base + r];
            float v = (float)labels[gr];
            float4 vv = make_float4(v, v, v, v);
            reinterpret_cast<float4*>(out + (size_t)gr * L_DIM + nBase)[c] = vv;
        }
        return;
    }

    extern __shared__ __align__(1024) char smem[];
    uint32_t sb = smem_u32(smem);

    int lane = tid & 31, wid = tid >> 5;
    int warp_m = wid & 1;        // M offset 32*warp_m
    int warp_n = wid >> 1;       // N offset 64*warp_n

    // ---- loader metadata ----
    // A: 64 rows x 64B = 4KB = 256 chunks, 2/thread
    int lrow0 = tid >> 2, lrow1 = 32 + (tid >> 2);
    int lchk  = tid & 3;
    int grow0 = (lrow0 < cnt) ? g_perm[base + lrow0] : -1;
    int grow1 = (lrow1 < cnt) ? g_perm[base + lrow1] : -1;
    uint32_t dA0 = swz(lrow0, lchk);
    uint32_t dA1 = swz(lrow1, lchk);
    const __half* aP0 = g_hid + (size_t)(grow0 < 0 ? 0 : grow0) * H_DIM + lchk * 8;
    const __half* aP1 = g_hid + (size_t)(grow1 < 0 ? 0 : grow1) * H_DIM + lchk * 8;
    uint32_t szA0 = grow0 >= 0 ? 16u : 0u;
    uint32_t szA1 = grow1 >= 0 ? 16u : 0u;
    // B: 128 rows x 64B = 8KB = 512 chunks, 4/thread (rows tid>>2 + 32i, same swizzle phase)
    uint32_t dB0 = (uint32_t)A_BYTES + swz(tid >> 2, lchk);
    const __half* bP = g_W + (size_t)(g * L_DIM + nBase + (tid >> 2)) * H_DIM + lchk * 8;

    uint32_t acc[2][8][2];
    #pragma unroll
    for (int i = 0; i < 2; i++)
        #pragma unroll
        for (int j = 0; j < 8; j++) { acc[i][j][0] = 0u; acc[i][j][1] = 0u; }

    auto load_stage = [&](int c, uint32_t boff) {
        uint32_t s0 = sb + boff;
        int kOff = c * KS;
        CP_ASYNC16(s0 + dA0, aP0 + kOff, szA0);
        CP_ASYNC16(s0 + dA1, aP1 + kOff, szA1);
        #pragma unroll
        for (int i = 0; i < 4; i++)
            CP_ASYNC16(s0 + dB0 + (uint32_t)i * 2048u,
                       bP + (size_t)i * 32 * H_DIM + kOff, 16u);
        CP_COMMIT();
    };

    load_stage(0, 0);
    load_stage(1, STAGE_BYTES);

    uint32_t cur = 0;   // compute-buffer offset, cycles 0 -> 12K -> 24K -> 0
    #pragma unroll 1
    for (int c = 0; c < NC; c++) {
        if (c + 1 < NC) { CP_WAIT1(); }
        else            { CP_WAIT0(); }
        __syncthreads();
        if (c + 2 < NC) {
            uint32_t pre = cur + 2u * STAGE_BYTES;
            if (pre >= 3u * STAGE_BYTES) pre -= 3u * STAGE_BYTES;
            load_stage(c + 2, pre);
        }

        uint32_t Ab = sb + cur;
        uint32_t Bb = Ab + A_BYTES;
        cur += STAGE_BYTES;
        if (cur >= 3u * STAGE_BYTES) cur = 0;

        #pragma unroll
        for (int s = 0; s < 2; s++) {
            int ch = 2 * s + (lane >> 4);
            uint32_t b[4][4];
            #pragma unroll
            for (int nb = 0; nb < 4; nb++) {
                int row = warp_n * 64 + nb * 16 + (lane & 15);
                LDSM_X4(b[nb], Bb + swz(row, ch));
            }
            uint32_t a[2][4];
            #pragma unroll
            for (int mt = 0; mt < 2; mt++) {
                int row = warp_m * 32 + mt * 16 + (lane & 15);
                LDSM_X4(a[mt], Ab + swz(row, ch));
            }
            #pragma unroll
            for (int mt = 0; mt < 2; mt++)
                #pragma unroll
                for (int nt = 0; nt < 8; nt++) {
                    int nb = nt >> 1, hf = nt & 1;
                    mma16816h(acc[mt][nt], a[mt], b[nb][hf], b[nb][hf + 2]);
                }
        }
    }

    // ---- epilogue (unpack fp16 acc -> fp32, add bias, scatter) ----
    int rl = lane >> 2;
    int cl = (lane & 3) * 2;
    const float* bptr = bias + g * L_DIM + nBase + warp_n * 64 + cl;

    #pragma unroll
    for (int mt = 0; mt < 2; mt++)
        #pragma unroll
        for (int h = 0; h < 2; h++) {
            int r = warp_m * 32 + mt * 16 + rl + h * 8;
            int gr = (r < cnt) ? g_perm[base + r] : -1;
            if (gr < 0) continue;
            float* orow = out + (size_t)gr * L_DIM + nBase + warp_n * 64 + cl;
            #pragma unroll
            for (int nt = 0; nt < 8; nt++) {
                __half2 hv = *reinterpret_cast<__half2*>(&acc[mt][nt][h]);
                float2 fv = __half22float2(hv);
                float2 bv = *reinterpret_cast<const float2*>(bptr + nt * 8);
                float2 o;
                o.x = fv.x + bv.x;
                o.y = fv.y + bv.y;
                *reinterpret_cast<float2*>(orow + nt * 8) = o;
            }
        }
}

// ---------------- launch ----------------
extern "C" void kernel_launch(void* const* d_in, const int* in_sizes, int n_in,
                              void* d_out, int out_size) {
    const float* hidden = (const float*)d_in[0];
    const float* W      = (const float*)d_in[1];
    const float* bias   = (const float*)d_in[2];
    const int*   group  = (const int*)d_in[3];
    const int*   labels = (const int*)d_in[4];
    float* out = (float*)d_out;

    // one-time setup on the (uncaptured) correctness call; reused during capture
    static cudaStream_t s2 = nullptr;
    static cudaEvent_t e1 = nullptr, e2 = nullptr;
    if (!s2) {
        cudaStreamCreateWithFlags(&s2, cudaStreamNonBlocking);
        cudaEventCreateWithFlags(&e1, cudaEventDisableTiming);
        cudaEventCreateWithFlags(&e2, cudaEventDisableTiming);
        cudaFuncSetAttribute(k_gemm_mma, cudaFuncAttributeMaxDynamicSharedMemorySize, SMEM_TOTAL);
    }

    // fork: prep runs on side stream concurrent with cvt on main stream
    cudaEventRecord(e1, 0);
    cudaStreamWaitEvent(s2, e1, 0);
    k_prep<<<1, 1024, 0, s2>>>(group);
    cudaEventRecord(e2, s2);

    k_cvt<<<(NW4 + NH4) / 512, 256>>>(W, hidden);

    // join: gemm waits for both
    cudaStreamWaitEvent(0, e2, 0);
    dim3 grid(L_DIM / BN, MAX_MTILES);
    k_gemm_mma<<<grid, NTHR, SMEM_TOTAL>>>(bias, labels, out);
}